// round 17
// baseline (speedup 1.0000x reference)
#include <cuda_runtime.h>
#include <math.h>

#define B_   32
#define T_   64
#define V_   32000
#define E_   512
#define H_   1024
#define BOS_ 1
#define EOS_ 3

#define TILE_V 256
#define NBLK_V 125   // 125*256 = 32000
#define KC     16

typedef unsigned long long ull;

// ---------------- device scratch ----------------
__device__ float g_h[2][B_ * H_];
__device__ float g_c[B_ * H_];
__device__ float g_pScore[NBLK_V * B_];
__device__ int   g_pIdx[NBLK_V * B_];
__device__ int   g_labels[T_ * B_];

__device__ __forceinline__ float sigm_(float x) {
    if (x >= 0.f) return 1.f / (1.f + expf(-x));
    float e = expf(x);
    return e / (1.f + e);
}

// packed fp32x2 helpers (sm_103a FFMA2 path)
__device__ __forceinline__ ull pack2(float x, float y) {
    ull r;
    unsigned a = __float_as_uint(x), b = __float_as_uint(y);
    asm("mov.b64 %0, {%1, %2};" : "=l"(r) : "r"(a), "r"(b));
    return r;
}
__device__ __forceinline__ void unpack2(ull v, float& lo, float& hi) {
    unsigned a, b;
    asm("mov.b64 {%0, %1}, %2;" : "=r"(a), "=r"(b) : "l"(v));
    lo = __uint_as_float(a); hi = __uint_as_float(b);
}
#define FMA2(acc, a, b) asm("fma.rn.f32x2 %0, %1, %2, %0;" : "+l"(acc) : "l"(a), "l"(b))

// ================= score kernel v3 =================
// C[v][b] = dot(W_hv[v,:], h[b,:]) + bias + gumbel; argmax per b.
// 125 blocks x 128 threads. Block tile 256v x 32b. Thread tile 8v x 8b,
// packed f32x2 over b-pairs. v-assignment: v_local = 2*(vg+32i)+e.
__global__ __launch_bounds__(128) void score_kernel(
        int cur,
        const float* __restrict__ Whv,
        const float* __restrict__ bhv,
        const float* __restrict__ u_t) {
    __shared__ float sW[2][KC * 256];   // [k][v_local]
    __shared__ float sH[2][KC * 34];    // [k][b], pad 34

    const int tid = threadIdx.x;
    const int vg = tid & 31;            // 32 v-groups
    const int bg = tid >> 5;            // 4 b-groups of 8
    const int vBase = blockIdx.x * TILE_V;
    const float* __restrict__ h = g_h[cur];

    ull acc2[8][4];                     // [v (2i+e)][b-pair]
#pragma unroll
    for (int i = 0; i < 8; i++)
#pragma unroll
        for (int j = 0; j < 4; j++) acc2[i][j] = 0ull;

    // staging roles: W rows tid and tid+128 ; h: b=tid>>2, q=tid&3
    const float* __restrict__ WrowA = Whv + (size_t)(vBase + tid) * H_;
    const float* __restrict__ WrowB = Whv + (size_t)(vBase + tid + 128) * H_;
    const int hb = tid >> 2, hq = tid & 3;

    float4 wA0, wA1, wA2, wA3, wB0, wB1, wB2, wB3, hr;

    // preload chunk 0
    wA0 = *reinterpret_cast<const float4*>(WrowA + 0);
    wA1 = *reinterpret_cast<const float4*>(WrowA + 4);
    wA2 = *reinterpret_cast<const float4*>(WrowA + 8);
    wA3 = *reinterpret_cast<const float4*>(WrowA + 12);
    wB0 = *reinterpret_cast<const float4*>(WrowB + 0);
    wB1 = *reinterpret_cast<const float4*>(WrowB + 4);
    wB2 = *reinterpret_cast<const float4*>(WrowB + 8);
    wB3 = *reinterpret_cast<const float4*>(WrowB + 12);
    hr  = *reinterpret_cast<const float4*>(h + (size_t)hb * H_ + hq * 4);
    {
        float* dW = &sW[0][0];
        dW[0 * 256 + tid] = wA0.x; dW[1 * 256 + tid] = wA0.y;
        dW[2 * 256 + tid] = wA0.z; dW[3 * 256 + tid] = wA0.w;
        dW[4 * 256 + tid] = wA1.x; dW[5 * 256 + tid] = wA1.y;
        dW[6 * 256 + tid] = wA1.z; dW[7 * 256 + tid] = wA1.w;
        dW[8 * 256 + tid] = wA2.x; dW[9 * 256 + tid] = wA2.y;
        dW[10 * 256 + tid] = wA2.z; dW[11 * 256 + tid] = wA2.w;
        dW[12 * 256 + tid] = wA3.x; dW[13 * 256 + tid] = wA3.y;
        dW[14 * 256 + tid] = wA3.z; dW[15 * 256 + tid] = wA3.w;
        dW[0 * 256 + 128 + tid] = wB0.x; dW[1 * 256 + 128 + tid] = wB0.y;
        dW[2 * 256 + 128 + tid] = wB0.z; dW[3 * 256 + 128 + tid] = wB0.w;
        dW[4 * 256 + 128 + tid] = wB1.x; dW[5 * 256 + 128 + tid] = wB1.y;
        dW[6 * 256 + 128 + tid] = wB1.z; dW[7 * 256 + 128 + tid] = wB1.w;
        dW[8 * 256 + 128 + tid] = wB2.x; dW[9 * 256 + 128 + tid] = wB2.y;
        dW[10 * 256 + 128 + tid] = wB2.z; dW[11 * 256 + 128 + tid] = wB2.w;
        dW[12 * 256 + 128 + tid] = wB3.x; dW[13 * 256 + 128 + tid] = wB3.y;
        dW[14 * 256 + 128 + tid] = wB3.z; dW[15 * 256 + 128 + tid] = wB3.w;
        float* dH = &sH[0][0];
        dH[(hq * 4 + 0) * 34 + hb] = hr.x;
        dH[(hq * 4 + 1) * 34 + hb] = hr.y;
        dH[(hq * 4 + 2) * 34 + hb] = hr.z;
        dH[(hq * 4 + 3) * 34 + hb] = hr.w;
    }
    __syncthreads();

    const int NT = H_ / KC;   // 64
    for (int c = 0; c < NT; c++) {
        const int cb = c & 1, nb = (c + 1) & 1;
        if (c + 1 < NT) {
            const float* pA = WrowA + (c + 1) * KC;
            const float* pB = WrowB + (c + 1) * KC;
            wA0 = *reinterpret_cast<const float4*>(pA + 0);
            wA1 = *reinterpret_cast<const float4*>(pA + 4);
            wA2 = *reinterpret_cast<const float4*>(pA + 8);
            wA3 = *reinterpret_cast<const float4*>(pA + 12);
            wB0 = *reinterpret_cast<const float4*>(pB + 0);
            wB1 = *reinterpret_cast<const float4*>(pB + 4);
            wB2 = *reinterpret_cast<const float4*>(pB + 8);
            wB3 = *reinterpret_cast<const float4*>(pB + 12);
            hr  = *reinterpret_cast<const float4*>(h + (size_t)hb * H_ + (c + 1) * KC + hq * 4);
        }
        const float* cW = &sW[cb][0];
        const float* cH = &sH[cb][0];
#pragma unroll
        for (int k = 0; k < KC; k++) {
            ull hp0 = *reinterpret_cast<const ull*>(cH + k * 34 + bg * 8 + 0);
            ull hp1 = *reinterpret_cast<const ull*>(cH + k * 34 + bg * 8 + 2);
            ull hp2 = *reinterpret_cast<const ull*>(cH + k * 34 + bg * 8 + 4);
            ull hp3 = *reinterpret_cast<const ull*>(cH + k * 34 + bg * 8 + 6);
#pragma unroll
            for (int i = 0; i < 4; i++) {
                float2 w2 = *reinterpret_cast<const float2*>(cW + k * 256 + 2 * (vg + 32 * i));
                ull ww0 = pack2(w2.x, w2.x);
                ull ww1 = pack2(w2.y, w2.y);
                FMA2(acc2[2 * i][0], ww0, hp0); FMA2(acc2[2 * i][1], ww0, hp1);
                FMA2(acc2[2 * i][2], ww0, hp2); FMA2(acc2[2 * i][3], ww0, hp3);
                FMA2(acc2[2 * i + 1][0], ww1, hp0); FMA2(acc2[2 * i + 1][1], ww1, hp1);
                FMA2(acc2[2 * i + 1][2], ww1, hp2); FMA2(acc2[2 * i + 1][3], ww1, hp3);
            }
        }
        if (c + 1 < NT) {
            float* dW = &sW[nb][0];
            dW[0 * 256 + tid] = wA0.x; dW[1 * 256 + tid] = wA0.y;
            dW[2 * 256 + tid] = wA0.z; dW[3 * 256 + tid] = wA0.w;
            dW[4 * 256 + tid] = wA1.x; dW[5 * 256 + tid] = wA1.y;
            dW[6 * 256 + tid] = wA1.z; dW[7 * 256 + tid] = wA1.w;
            dW[8 * 256 + tid] = wA2.x; dW[9 * 256 + tid] = wA2.y;
            dW[10 * 256 + tid] = wA2.z; dW[11 * 256 + tid] = wA2.w;
            dW[12 * 256 + tid] = wA3.x; dW[13 * 256 + tid] = wA3.y;
            dW[14 * 256 + tid] = wA3.z; dW[15 * 256 + tid] = wA3.w;
            dW[0 * 256 + 128 + tid] = wB0.x; dW[1 * 256 + 128 + tid] = wB0.y;
            dW[2 * 256 + 128 + tid] = wB0.z; dW[3 * 256 + 128 + tid] = wB0.w;
            dW[4 * 256 + 128 + tid] = wB1.x; dW[5 * 256 + 128 + tid] = wB1.y;
            dW[6 * 256 + 128 + tid] = wB1.z; dW[7 * 256 + 128 + tid] = wB1.w;
            dW[8 * 256 + 128 + tid] = wB2.x; dW[9 * 256 + 128 + tid] = wB2.y;
            dW[10 * 256 + 128 + tid] = wB2.z; dW[11 * 256 + 128 + tid] = wB2.w;
            dW[12 * 256 + 128 + tid] = wB3.x; dW[13 * 256 + 128 + tid] = wB3.y;
            dW[14 * 256 + 128 + tid] = wB3.z; dW[15 * 256 + 128 + tid] = wB3.w;
            float* dH = &sH[nb][0];
            dH[(hq * 4 + 0) * 34 + hb] = hr.x;
            dH[(hq * 4 + 1) * 34 + hb] = hr.y;
            dH[(hq * 4 + 2) * 34 + hb] = hr.z;
            dH[(hq * 4 + 3) * 34 + hb] = hr.w;
        }
        __syncthreads();
    }

    // ---- epilogue: bias + gumbel + argmax (warp bg owns b in [bg*8, bg*8+8)) ----
    float bvx[8];
#pragma unroll
    for (int i = 0; i < 4; i++) {
        float2 t = *reinterpret_cast<const float2*>(bhv + vBase + 2 * (vg + 32 * i));
        bvx[2 * i] = t.x; bvx[2 * i + 1] = t.y;
    }
#pragma unroll
    for (int bl = 0; bl < 8; bl++) {
        const int b = bg * 8 + bl;
        const int bp = bl >> 1, half = bl & 1;
        const float* ub = u_t + (size_t)b * V_ + vBase;
        float bs = -3.402823466e38f;
        int bv = 0;
#pragma unroll
        for (int i = 0; i < 4; i++) {
            float2 u2 = *reinterpret_cast<const float2*>(ub + 2 * (vg + 32 * i));
            float lo0, hi0, lo1, hi1;
            unpack2(acc2[2 * i][bp], lo0, hi0);
            unpack2(acc2[2 * i + 1][bp], lo1, hi1);
            float s0 = (half ? hi0 : lo0) + bvx[2 * i]
                     + (-logf(-logf(u2.x + 1e-10f) + 1e-10f));
            float s1 = (half ? hi1 : lo1) + bvx[2 * i + 1]
                     + (-logf(-logf(u2.y + 1e-10f) + 1e-10f));
            int v0 = vBase + 2 * vg + 64 * i;
            if (s0 > bs) { bs = s0; bv = v0; }
            if (s1 > bs) { bs = s1; bv = v0 + 1; }
        }
#pragma unroll
        for (int off = 16; off > 0; off >>= 1) {
            float os = __shfl_xor_sync(0xffffffffu, bs, off);
            int   ov = __shfl_xor_sync(0xffffffffu, bv, off);
            if (os > bs || (os == bs && ov < bv)) { bs = os; bv = ov; }
        }
        if ((tid & 31) == 0) {
            g_pScore[blockIdx.x * B_ + b] = bs;
            g_pIdx[blockIdx.x * B_ + b]   = bv;
        }
    }
}

// ================= LSTM step v3 =================
// grid 64, 128 threads. Block tile: m in [blk*16,+16) x 4 gates = 64 rows x 32 b.
// Thread tile 4 rows x 4 b, packed f32x2 over b-pairs. Fused final argmax + activation.
__global__ __launch_bounds__(128) void lstm_kernel(
        int cur,
        const float* __restrict__ emb,
        const float* __restrict__ Wih,
        const float* __restrict__ Whh,
        const float* __restrict__ bih,
        const float* __restrict__ bhh,
        int useArgmax, int tstep) {
    __shared__ float sW[2][KC * 64];    // [k][tile row]
    __shared__ float sX[2][KC * 34];    // [k][b], pad 34
    __shared__ float gateS[64 * 33];
    __shared__ int   labelS[B_];
    __shared__ float rs[4 * 32];
    __shared__ int   ri[4 * 32];

    const int tid = threadIdx.x;
    const int rg = tid & 15;            // 16 row-groups of 4
    const int bg = tid >> 4;            // 8 b-groups of 4
    const int m0 = blockIdx.x * 16;

    // ---- prologue: deterministic final argmax over 125 partials ----
    if (useArgmax) {
        int r = tid & 3, b = tid >> 2;
        float bb = -3.402823466e38f;
        int   bi = 0x7fffffff;
        for (int j = r; j < NBLK_V; j += 4) {
            float s = g_pScore[j * B_ + b];
            int   v = g_pIdx[j * B_ + b];
            if (s > bb || (s == bb && v < bi)) { bb = s; bi = v; }
        }
        rs[r * 32 + b] = bb; ri[r * 32 + b] = bi;
        __syncthreads();
        if (tid < 32) {
            float m = rs[tid]; int mi = ri[tid];
#pragma unroll
            for (int r2 = 1; r2 < 4; r2++) {
                float s = rs[r2 * 32 + tid];
                int   v = ri[r2 * 32 + tid];
                if (s > m || (s == m && v < mi)) { m = s; mi = v; }
            }
            labelS[tid] = mi;
            if (blockIdx.x == 0) g_labels[tstep * B_ + tid] = mi;
        }
    } else {
        if (tid < 32) labelS[tid] = BOS_;
    }
    __syncthreads();

    const float* __restrict__ hin = g_h[cur];
    float* __restrict__ hout = g_h[cur ^ 1];

    // staging roles: W -> row r=tid>>1 (of 64), half wh=tid&1 (8 floats each)
    //                x -> b=tid>>2, quarter xq=tid&3
    const int wr = tid >> 1, wh = tid & 1;
    const int wGate = wr >> 4, wMloc = wr & 15;
    const float* __restrict__ rowIh = Wih + (size_t)(wGate * H_ + m0 + wMloc) * E_;
    const float* __restrict__ rowHh = Whh + (size_t)(wGate * H_ + m0 + wMloc) * H_;
    const int xb = tid >> 2, xq = tid & 3;
    const float* __restrict__ embRow = emb + (size_t)labelS[xb] * E_;

    ull acc2[4][2];                     // [row j][b-pair]
#pragma unroll
    for (int i = 0; i < 4; i++) { acc2[i][0] = 0ull; acc2[i][1] = 0ull; }

    float4 wq0, wq1, xr;
    // preload chunk 0 (emb region)
    wq0 = *reinterpret_cast<const float4*>(rowIh + wh * 8);
    wq1 = *reinterpret_cast<const float4*>(rowIh + wh * 8 + 4);
    xr  = *reinterpret_cast<const float4*>(embRow + xq * 4);
    {
        float* dW = &sW[0][0];
        dW[(wh * 8 + 0) * 64 + wr] = wq0.x; dW[(wh * 8 + 1) * 64 + wr] = wq0.y;
        dW[(wh * 8 + 2) * 64 + wr] = wq0.z; dW[(wh * 8 + 3) * 64 + wr] = wq0.w;
        dW[(wh * 8 + 4) * 64 + wr] = wq1.x; dW[(wh * 8 + 5) * 64 + wr] = wq1.y;
        dW[(wh * 8 + 6) * 64 + wr] = wq1.z; dW[(wh * 8 + 7) * 64 + wr] = wq1.w;
        float* dX = &sX[0][0];
        dX[(xq * 4 + 0) * 34 + xb] = xr.x; dX[(xq * 4 + 1) * 34 + xb] = xr.y;
        dX[(xq * 4 + 2) * 34 + xb] = xr.z; dX[(xq * 4 + 3) * 34 + xb] = xr.w;
    }
    __syncthreads();

    const int NT = (E_ + H_) / KC;   // 96 ; chunks 0..31 = emb, 32..95 = h
    for (int c = 0; c < NT; c++) {
        const int cb = c & 1, nb = (c + 1) & 1;
        if (c + 1 < NT) {
            const int cn = c + 1;
            const float* wsrc = (cn < 32) ? rowIh + cn * KC + wh * 8
                                          : rowHh + (cn - 32) * KC + wh * 8;
            const float* xsrc = (cn < 32) ? embRow + cn * KC + xq * 4
                                          : hin + (size_t)xb * H_ + (cn - 32) * KC + xq * 4;
            wq0 = *reinterpret_cast<const float4*>(wsrc);
            wq1 = *reinterpret_cast<const float4*>(wsrc + 4);
            xr  = *reinterpret_cast<const float4*>(xsrc);
        }
        const float* cW = &sW[cb][0];
        const float* cX = &sX[cb][0];
#pragma unroll
        for (int k = 0; k < KC; k++) {
            float4 w4 = *reinterpret_cast<const float4*>(cW + k * 64 + rg * 4);
            ull hp0 = *reinterpret_cast<const ull*>(cX + k * 34 + bg * 4);
            ull hp1 = *reinterpret_cast<const ull*>(cX + k * 34 + bg * 4 + 2);
            ull ww;
            ww = pack2(w4.x, w4.x); FMA2(acc2[0][0], ww, hp0); FMA2(acc2[0][1], ww, hp1);
            ww = pack2(w4.y, w4.y); FMA2(acc2[1][0], ww, hp0); FMA2(acc2[1][1], ww, hp1);
            ww = pack2(w4.z, w4.z); FMA2(acc2[2][0], ww, hp0); FMA2(acc2[2][1], ww, hp1);
            ww = pack2(w4.w, w4.w); FMA2(acc2[3][0], ww, hp0); FMA2(acc2[3][1], ww, hp1);
        }
        if (c + 1 < NT) {
            float* dW = &sW[nb][0];
            dW[(wh * 8 + 0) * 64 + wr] = wq0.x; dW[(wh * 8 + 1) * 64 + wr] = wq0.y;
            dW[(wh * 8 + 2) * 64 + wr] = wq0.z; dW[(wh * 8 + 3) * 64 + wr] = wq0.w;
            dW[(wh * 8 + 4) * 64 + wr] = wq1.x; dW[(wh * 8 + 5) * 64 + wr] = wq1.y;
            dW[(wh * 8 + 6) * 64 + wr] = wq1.z; dW[(wh * 8 + 7) * 64 + wr] = wq1.w;
            float* dX = &sX[nb][0];
            dX[(xq * 4 + 0) * 34 + xb] = xr.x; dX[(xq * 4 + 1) * 34 + xb] = xr.y;
            dX[(xq * 4 + 2) * 34 + xb] = xr.z; dX[(xq * 4 + 3) * 34 + xb] = xr.w;
        }
        __syncthreads();
    }

    // ---- gather gates, fused activation ----
#pragma unroll
    for (int j = 0; j < 4; j++) {
#pragma unroll
        for (int bp = 0; bp < 2; bp++) {
            float lo, hi;
            unpack2(acc2[j][bp], lo, hi);
            gateS[(rg * 4 + j) * 33 + bg * 4 + 2 * bp]     = lo;
            gateS[(rg * 4 + j) * 33 + bg * 4 + 2 * bp + 1] = hi;
        }
    }
    __syncthreads();
#pragma unroll
    for (int it = 0; it < 4; it++) {
        int p = it * 128 + tid;
        int mloc = p >> 5, b = p & 31;
        int mg = m0 + mloc;
        float gi = gateS[(mloc) * 33 + b]      + bih[mg]          + bhh[mg];
        float gf = gateS[(16 + mloc) * 33 + b] + bih[H_ + mg]     + bhh[H_ + mg];
        float gg = gateS[(32 + mloc) * 33 + b] + bih[2 * H_ + mg] + bhh[2 * H_ + mg];
        float go = gateS[(48 + mloc) * 33 + b] + bih[3 * H_ + mg] + bhh[3 * H_ + mg];
        float co = g_c[b * H_ + mg];
        float cn = sigm_(gf) * co + sigm_(gi) * tanhf(gg);
        float hn = sigm_(go) * tanhf(cn);
        g_c[b * H_ + mg] = cn;
        hout[b * H_ + mg] = hn;
    }
}

// ---------------- h0 = image_hidden @ W_proj^T + b_proj ; c = 0 (runs once) ----------------
__global__ __launch_bounds__(128) void inith_kernel(
        const float* __restrict__ img,
        const float* __restrict__ Wproj,
        const float* __restrict__ bproj) {
    __shared__ float sT[128 * 33];
    const int tid = threadIdx.x, lane = tid & 31, w = tid >> 5;
    const int m0 = blockIdx.x * 8 + w * 2;
    float a0 = 0.f, a1 = 0.f;
    for (int dc = 0; dc < 1024; dc += 128) {
        for (int idx = tid; idx < B_ * 128; idx += 128) {
            int b = idx >> 7, k = idx & 127;
            sT[k * 33 + b] = img[b * 1024 + dc + k];
        }
        __syncthreads();
#pragma unroll 2
        for (int k4 = 0; k4 < 32; k4++) {
            float x0 = sT[(k4 * 4 + 0) * 33 + lane];
            float x1 = sT[(k4 * 4 + 1) * 33 + lane];
            float x2 = sT[(k4 * 4 + 2) * 33 + lane];
            float x3 = sT[(k4 * 4 + 3) * 33 + lane];
            float4 w0 = *reinterpret_cast<const float4*>(
                Wproj + (size_t)m0 * 1024 + dc + k4 * 4);
            float4 w1 = *reinterpret_cast<const float4*>(
                Wproj + (size_t)(m0 + 1) * 1024 + dc + k4 * 4);
            a0 = fmaf(w0.x, x0, fmaf(w0.y, x1, fmaf(w0.z, x2, fmaf(w0.w, x3, a0))));
            a1 = fmaf(w1.x, x0, fmaf(w1.y, x1, fmaf(w1.z, x2, fmaf(w1.w, x3, a1))));
        }
        __syncthreads();
    }
    g_h[0][lane * H_ + m0]     = a0 + bproj[m0];
    g_h[0][lane * H_ + m0 + 1] = a1 + bproj[m0 + 1];
    g_c[lane * H_ + m0]     = 0.f;
    g_c[lane * H_ + m0 + 1] = 0.f;
}

// ---------------- zero-fill the logits region ----------------
__global__ void zero_kernel(float4* __restrict__ p, long long n4) {
    long long i = (long long)blockIdx.x * blockDim.x + threadIdx.x;
    long long stride = (long long)gridDim.x * blockDim.x;
    float4 z = make_float4(0.f, 0.f, 0.f, 0.f);
    for (; i < n4; i += stride) p[i] = z;
}

// ---------------- assemble outputs ----------------
__global__ __launch_bounds__(256) void final_kernel(float* __restrict__ out) {
    __shared__ int fe[B_];
    const int tid = threadIdx.x;
    if (tid < B_) {
        int f = T_ - 1;
        for (int t = 0; t < T_ - 1; t++) {
            if (g_labels[t * B_ + tid] == EOS_) { f = t; break; }
        }
        fe[tid] = f;
        out[(long long)B_ * T_ + (long long)B_ * T_ * V_ + tid] = (float)(f + 1);
    }
    __syncthreads();
    for (int idx = tid; idx < B_ * T_; idx += 256) {
        int b = idx >> 6, t = idx & 63;
        int lab = (t == T_ - 1) ? EOS_ : g_labels[t * B_ + b];
        int f = fe[b];
        out[b * T_ + t] = (t < f) ? (float)lab : 0.f;
        int col = (t < f) ? lab : 0;
        out[(long long)B_ * T_ + (long long)(b * T_ + t) * V_ + col] = 1.0f;
    }
}

// ---------------- host launcher ----------------
extern "C" void kernel_launch(void* const* d_in, const int* in_sizes, int n_in,
                              void* d_out, int out_size) {
    const float* img   = (const float*)d_in[0];
    const float* gum   = (const float*)d_in[1];
    const float* Wproj = (const float*)d_in[2];
    const float* bproj = (const float*)d_in[3];
    const float* emb   = (const float*)d_in[4];
    const float* Wih   = (const float*)d_in[5];
    const float* Whh   = (const float*)d_in[6];
    const float* bih   = (const float*)d_in[7];
    const float* bhh   = (const float*)d_in[8];
    const float* Whv   = (const float*)d_in[9];
    const float* bhv   = (const float*)d_in[10];
    float* out = (float*)d_out;

    zero_kernel<<<4096, 256>>>(reinterpret_cast<float4*>(out + B_ * T_),
                               (long long)B_ * T_ * V_ / 4);

    inith_kernel<<<128, 128>>>(img, Wproj, bproj);
    lstm_kernel<<<64, 128>>>(0, emb, Wih, Whh, bih, bhh, /*useArgmax=*/0, 0);

    int cur = 1;
    for (int t = 0; t < T_ - 1; t++) {
        score_kernel<<<NBLK_V, 128>>>(cur, Whv, bhv, gum + (size_t)t * B_ * V_);
        lstm_kernel<<<64, 128>>>(cur, emb, Wih, Whh, bih, bhh, /*useArgmax=*/1, t);
        cur ^= 1;
    }

    final_kernel<<<1, 256>>>(out);
}